// round 5
// baseline (speedup 1.0000x reference)
#include <cuda_runtime.h>
#include <cuda_fp16.h>
#include <math.h>

#define Bb   512
#define Hh   256
#define Ld   256
#define Tt   64
#define Vv   128
#define NL   2
#define G    4
#define NTH  1024

// ---------------- packed weight scratch (transposed + k-interleaved) ----------------
#define OFF_ATTN 0          // 512x256  -> 131072 floats
#define OFF_COMB 131072     // 512x256  -> 131072
#define OFF_GIH  262144     // 2 x 256x768 -> 393216
#define OFF_GHH  655360     // 2 x 256x768 -> 393216
#define OFF_OUT  1048576    // 256x128  -> 32768
#define PACK_TOTAL 1081344

__device__ __align__(16) float  g_pack[PACK_TOTAL];
__device__ __align__(16) __half g_enc[(size_t)Bb * Hh * Ld];   // fp16 encoder memory

__global__ void pack_kernel(const float* __restrict__ aw, const float* __restrict__ cw,
                            const float* __restrict__ gih, const float* __restrict__ ghh,
                            const float* __restrict__ ow)
{
    int i = blockIdx.x * blockDim.x + threadIdx.x;
    if (i >= PACK_TOTAL) return;
    float v;
    if (i < 131072) {                       // attn: K=512, N=256
        int c = i & 3, j = (i >> 2) & 255, k4 = i >> 10;
        v = aw[j * 512 + k4 * 4 + c];
    } else if (i < 262144) {                // comb: K=512, N=256
        int r = i - 131072;
        int c = r & 3, j = (r >> 2) & 255, k4 = r >> 10;
        v = cw[j * 512 + k4 * 4 + c];
    } else if (i < 655360) {                // gru ih: per layer K=256, N=768
        int r = i - 262144;
        int layer = r / 196608; int q = r % 196608;
        int c = q & 3; int t2 = q >> 2; int j = t2 % 768; int k4 = t2 / 768;
        v = gih[layer * 196608 + j * 256 + k4 * 4 + c];
    } else if (i < 1048576) {               // gru hh
        int r = i - 655360;
        int layer = r / 196608; int q = r % 196608;
        int c = q & 3; int t2 = q >> 2; int j = t2 % 768; int k4 = t2 / 768;
        v = ghh[layer * 196608 + j * 256 + k4 * 4 + c];
    } else {                                // out: K=256, N=128
        int r = i - 1048576;
        int c = r & 3, j = (r >> 2) & 127, k4 = r >> 9;
        v = ow[j * 256 + k4 * 4 + c];
    }
    g_pack[i] = v;
}

// fp32 -> fp16 encoder pack
__global__ void pack_enc_kernel(const float* __restrict__ x)
{
    size_t i = (size_t)blockIdx.x * blockDim.x + threadIdx.x;   // i over float4s
    float4 v = ((const float4*)x)[i];
    __half2 h0 = __floats2half2_rn(v.x, v.y);
    __half2 h1 = __floats2half2_rn(v.z, v.w);
    uint2 o;
    o.x = *(unsigned*)&h0;
    o.y = *(unsigned*)&h1;
    ((uint2*)g_enc)[i] = o;
}

// ---------------- f32x2 packed math helpers (sm_10x FFMA2) ----------------
typedef unsigned long long u64;

__device__ __forceinline__ void fma2(u64& d, u64 a, u64 b) {
    asm("fma.rn.f32x2 %0, %1, %2, %0;" : "+l"(d) : "l"(a), "l"(b));
}
__device__ __forceinline__ float sum2(u64 v) {
    float lo = __uint_as_float((unsigned)v);
    float hi = __uint_as_float((unsigned)(v >> 32));
    return lo + hi;
}

// ---------------- vectorized block reduction (4 values, 32 warps) ----------------
__device__ __forceinline__ void block_reduce4(float v[G], float* sm, int tid, bool is_max) {
    __syncthreads();
    #pragma unroll
    for (int g = 0; g < G; g++) {
        #pragma unroll
        for (int o = 16; o > 0; o >>= 1) {
            float oth = __shfl_xor_sync(0xffffffffu, v[g], o);
            v[g] = is_max ? fmaxf(v[g], oth) : (v[g] + oth);
        }
    }
    int wid = tid >> 5;
    if ((tid & 31) == 0) {
        #pragma unroll
        for (int g = 0; g < G; g++) sm[wid * G + g] = v[g];
    }
    __syncthreads();
    #pragma unroll
    for (int g = 0; g < G; g++) {
        float r = sm[g];
        #pragma unroll
        for (int w = 1; w < 32; w++)
            r = is_max ? fmaxf(r, sm[w * G + g]) : (r + sm[w * G + g]);
        v[g] = r;
    }
}

// ---------------- main persistent decoder kernel ----------------
// 128 CTAs x 1024 threads. Each CTA owns 4 batch rows for all 64 steps.
// Quarter q = tid>>8 splits every matvec's K dimension 4 ways.
__global__ __launch_bounds__(NTH)
void decoder_kernel(const int*   __restrict__ y,      // [B,T]
                    const float* __restrict__ emb,    // [V,H]
                    const float* __restrict__ attn_b, // [L]
                    const float* __restrict__ comb_b, // [H]
                    const float* __restrict__ gbi,    // [2,768]
                    const float* __restrict__ gbh,    // [2,768]
                    const float* __restrict__ out_b,  // [V]
                    float* __restrict__ outp,         // [B,V,T]
                    float* __restrict__ attnp)        // [B,T,L]
{
    extern __shared__ __align__(16) float smem[];
    float* s_e   = smem;                 // G*256        = 1024
    float* s_h   = s_e   + 1024;         // NL*G*256     = 2048
    float* s_aw  = s_h   + 2048;         // G*256        = 1024
    float* s_app = s_aw  + 1024;         // G*256        = 1024
    float* s_x   = s_app + 1024;         // G*256        = 1024
    float* s_p2  = s_x   + 1024;         // G*12*256     = 12288
    float* s_out = s_p2  + 12288;        // G*128*8      = 4096
    float* s_red = s_out + 4096;         // 32*G         = 128
    // total 22656 floats = 90624 bytes

    const int tid  = threadIdx.x;
    const int wid  = tid >> 5;
    const int lane = tid & 31;
    const int q    = tid >> 8;           // quarter 0..3
    const int jj   = tid & 255;
    const int b0   = blockIdx.x * G;

    const float* Pattn = g_pack + OFF_ATTN;
    const float* Pcomb = g_pack + OFF_COMB;
    const float* Pgih  = g_pack + OFF_GIH;
    const float* Pghh  = g_pack + OFF_GHH;
    const float* Pout  = g_pack + OFF_OUT;

    for (int i = tid; i < NL * G * Hh; i += NTH) s_h[i] = 0.f;
    __syncthreads();

    for (int t = 0; t < Tt; t++) {
        // -------- embedding lookup (teacher forcing; SOS=0 at t=0) --------
        {
            int g = tid >> 8, h = tid & 255;
            int tok = (t == 0) ? 0 : y[(b0 + g) * Tt + t - 1];
            s_e[g * Hh + h] = emb[tok * Hh + h];
        }
        __syncthreads();

        // -------- attention scores: quarter q = K-slice [q*128, q*128+128) --------
        {
            u64 acc[G] = {0, 0, 0, 0};
            const ulonglong2* W = (const ulonglong2*)Pattn + jj;
            const float* vb = (q < 2) ? s_e : s_h;   // [e | h0]
            const int kl = (q & 1) * 32;
            #pragma unroll 2
            for (int k4 = 0; k4 < 32; k4++) {
                ulonglong2 w = W[(q * 32 + k4) * 256];
                #pragma unroll
                for (int g = 0; g < G; g++) {
                    ulonglong2 xv = ((const ulonglong2*)(vb + g * Hh))[kl + k4];
                    fma2(acc[g], w.x, xv.x);
                    fma2(acc[g], w.y, xv.y);
                }
            }
            if (q != 0) {
                #pragma unroll
                for (int g = 0; g < G; g++)
                    s_p2[(g * 12 + (q - 1)) * Hh + jj] = sum2(acc[g]);
            }
            __syncthreads();

            // softmax over L per row (true values computed by quarter 0)
            float sc[G];
            #pragma unroll
            for (int g = 0; g < G; g++)
                sc[g] = (q == 0)
                    ? (sum2(acc[g]) + s_p2[(g * 12 + 0) * Hh + jj]
                                    + s_p2[(g * 12 + 1) * Hh + jj]
                                    + s_p2[(g * 12 + 2) * Hh + jj] + attn_b[jj])
                    : -1e30f;
            float m[G];
            #pragma unroll
            for (int g = 0; g < G; g++) m[g] = sc[g];
            block_reduce4(m, s_red, tid, true);
            float p[G];
            #pragma unroll
            for (int g = 0; g < G; g++) p[g] = (q == 0) ? __expf(sc[g] - m[g]) : 0.f;
            float s[G];
            #pragma unroll
            for (int g = 0; g < G; g++) s[g] = p[g];
            block_reduce4(s, s_red, tid, false);
            if (q == 0) {
                #pragma unroll
                for (int g = 0; g < G; g++) {
                    float a = p[g] * (1.f / s[g]);
                    s_aw[g * Ld + jj] = a;
                    attnp[((size_t)(b0 + g) * Tt + t) * Ld + jj] = a;
                }
            }
            __syncthreads();
        }

        // -------- applied = aw @ enc (fp16, 32 warps: 8 per batch row) --------
        {
            const int g = wid >> 3;                    // 8 warps per batch row
            const int hbase = (wid & 7) * 32;          // 32 h-values per warp
            const float4* awp = (const float4*)(s_aw + g * Ld);
            const float4 A0 = awp[lane * 2];
            const float4 A1 = awp[lane * 2 + 1];
            const uint4* xrow =
                (const uint4*)(g_enc + ((size_t)(b0 + g) * Hh + hbase) * Ld) + lane;
            #pragma unroll
            for (int it = 0; it < 32; it += 8) {
                uint4 xv[8];
                #pragma unroll
                for (int u = 0; u < 8; u++) xv[u] = xrow[(it + u) * 32];
                float d[8];
                #pragma unroll
                for (int u = 0; u < 8; u++) {
                    float2 f0 = __half22float2(*(__half2*)&xv[u].x);
                    float2 f1 = __half22float2(*(__half2*)&xv[u].y);
                    float2 f2 = __half22float2(*(__half2*)&xv[u].z);
                    float2 f3 = __half22float2(*(__half2*)&xv[u].w);
                    d[u] = f0.x * A0.x + f0.y * A0.y + f1.x * A0.z + f1.y * A0.w
                         + f2.x * A1.x + f2.y * A1.y + f3.x * A1.z + f3.y * A1.w;
                }
                #pragma unroll
                for (int u = 0; u < 8; u++) {
                    #pragma unroll
                    for (int o = 16; o > 0; o >>= 1)
                        d[u] += __shfl_xor_sync(0xffffffffu, d[u], o);
                }
                if (lane == 0) {
                    #pragma unroll
                    for (int u = 0; u < 8; u++) s_app[g * Hh + hbase + it + u] = d[u];
                }
            }
        }
        __syncthreads();

        // -------- combine: quarters split [applied | e] K=512 into 4x128 --------
        {
            u64 acc[G] = {0, 0, 0, 0};
            const ulonglong2* W = (const ulonglong2*)Pcomb + jj;
            const float* vb = (q < 2) ? s_app : s_e;
            const int kl = (q & 1) * 32;
            #pragma unroll 2
            for (int k4 = 0; k4 < 32; k4++) {
                ulonglong2 w = W[(q * 32 + k4) * 256];
                #pragma unroll
                for (int g = 0; g < G; g++) {
                    ulonglong2 xv = ((const ulonglong2*)(vb + g * Hh))[kl + k4];
                    fma2(acc[g], w.x, xv.x);
                    fma2(acc[g], w.y, xv.y);
                }
            }
            if (q != 0) {
                #pragma unroll
                for (int g = 0; g < G; g++)
                    s_p2[(g * 12 + (q - 1)) * Hh + jj] = sum2(acc[g]);
            }
            __syncthreads();
            if (q == 0) {
                const float bj = comb_b[jj];
                #pragma unroll
                for (int g = 0; g < G; g++)
                    s_x[g * Hh + jj] = fmaxf(sum2(acc[g])
                        + s_p2[(g * 12 + 0) * Hh + jj]
                        + s_p2[(g * 12 + 1) * Hh + jj]
                        + s_p2[(g * 12 + 2) * Hh + jj] + bj, 0.f);
            }
            __syncthreads();
        }

        // -------- GRU layers: quarters = {ih-lo, ih-hi, hh-lo, hh-hi} --------
        #pragma unroll
        for (int l = 0; l < NL; l++) {
            u64 a0[G] = {0,0,0,0}, a1[G] = {0,0,0,0}, a2[G] = {0,0,0,0};
            const ulonglong2* W =
                (const ulonglong2*)(((q < 2) ? Pgih : Pghh) + l * 196608) + jj;
            const float* vb = (q < 2) ? s_x : (s_h + l * G * Hh);
            const int kl = (q & 1) * 32;
            #pragma unroll 2
            for (int k4 = 0; k4 < 32; k4++) {
                int k4g = kl + k4;
                ulonglong2 w0 = W[k4g * 768];
                ulonglong2 w1 = W[k4g * 768 + 256];
                ulonglong2 w2 = W[k4g * 768 + 512];
                #pragma unroll
                for (int g = 0; g < G; g++) {
                    ulonglong2 xv = ((const ulonglong2*)(vb + g * Hh))[k4g];
                    fma2(a0[g], w0.x, xv.x); fma2(a0[g], w0.y, xv.y);
                    fma2(a1[g], w1.x, xv.x); fma2(a1[g], w1.y, xv.y);
                    fma2(a2[g], w2.x, xv.x); fma2(a2[g], w2.y, xv.y);
                }
            }
            if (q != 0) {
                #pragma unroll
                for (int g = 0; g < G; g++) {
                    s_p2[(g * 12 + (q - 1) * 3 + 0) * Hh + jj] = sum2(a0[g]);
                    s_p2[(g * 12 + (q - 1) * 3 + 1) * Hh + jj] = sum2(a1[g]);
                    s_p2[(g * 12 + (q - 1) * 3 + 2) * Hh + jj] = sum2(a2[g]);
                }
            }
            __syncthreads();
            if (q == 0) {
                const float bi0 = gbi[l * 768 + jj];
                const float bi1 = gbi[l * 768 + 256 + jj];
                const float bi2 = gbi[l * 768 + 512 + jj];
                const float bh0 = gbh[l * 768 + jj];
                const float bh1 = gbh[l * 768 + 256 + jj];
                const float bh2 = gbh[l * 768 + 512 + jj];
                #pragma unroll
                for (int g = 0; g < G; g++) {
                    float hprev = s_h[(l * G + g) * Hh + jj];
                    // ih = own (q0) + q1 partials (slices 0..2); hh = q2 (3..5) + q3 (6..8)
                    float i0 = sum2(a0[g]) + s_p2[(g * 12 + 0) * Hh + jj] + bi0;
                    float i1 = sum2(a1[g]) + s_p2[(g * 12 + 1) * Hh + jj] + bi1;
                    float i2 = sum2(a2[g]) + s_p2[(g * 12 + 2) * Hh + jj] + bi2;
                    float h0 = s_p2[(g * 12 + 3) * Hh + jj] + s_p2[(g * 12 + 6) * Hh + jj] + bh0;
                    float h1 = s_p2[(g * 12 + 4) * Hh + jj] + s_p2[(g * 12 + 7) * Hh + jj] + bh1;
                    float h2 = s_p2[(g * 12 + 5) * Hh + jj] + s_p2[(g * 12 + 8) * Hh + jj] + bh2;
                    float r = 1.f / (1.f + __expf(-(i0 + h0)));
                    float z = 1.f / (1.f + __expf(-(i1 + h1)));
                    float n = tanhf(i2 + r * h2);
                    float hn = (1.f - z) * n + z * hprev;
                    s_h[(l * G + g) * Hh + jj] = hn;
                    s_x[g * Hh + jj]           = hn;
                }
            }
            __syncthreads();
        }

        // -------- output projection (K split 8 ways) + log_softmax --------
        {
            int j  = tid & 127;
            int sl = tid >> 7;                   // 0..7, k4 slice of 8
            u64 acc[G] = {0, 0, 0, 0};
            const ulonglong2* W = (const ulonglong2*)Pout + j;
            #pragma unroll
            for (int k4 = sl * 8; k4 < sl * 8 + 8; k4++) {
                ulonglong2 w = W[k4 * 128];
                #pragma unroll
                for (int g = 0; g < G; g++) {
                    ulonglong2 hv = ((const ulonglong2*)(s_x + g * Hh))[k4];
                    fma2(acc[g], w.x, hv.x);
                    fma2(acc[g], w.y, hv.y);
                }
            }
            float* s_op = s_p2;                  // [G][8][128] = 4096 floats
            #pragma unroll
            for (int g = 0; g < G; g++) s_op[(g * 8 + sl) * 128 + j] = sum2(acc[g]);
            __syncthreads();

            float oacc[G];
            #pragma unroll
            for (int g = 0; g < G; g++) {
                if (tid < 128) {
                    float r = out_b[j];
                    #pragma unroll
                    for (int u = 0; u < 8; u++) r += s_op[(g * 8 + u) * 128 + j];
                    oacc[g] = r;
                } else {
                    oacc[g] = -1e30f;
                }
            }
            float m[G];
            #pragma unroll
            for (int g = 0; g < G; g++) m[g] = oacc[g];
            block_reduce4(m, s_red, tid, true);
            float p[G];
            #pragma unroll
            for (int g = 0; g < G; g++) p[g] = (tid < 128) ? __expf(oacc[g] - m[g]) : 0.f;
            float s[G];
            #pragma unroll
            for (int g = 0; g < G; g++) s[g] = p[g];
            block_reduce4(s, s_red, tid, false);
            if (tid < 128) {
                #pragma unroll
                for (int g = 0; g < G; g++)
                    s_out[(g * Vv + j) * 8 + (t & 7)] = oacc[g] - m[g] - logf(s[g]);
            }
        }

        // -------- flush staged outputs every 8 steps (1024 coalesced float4) --------
        __syncthreads();
        if ((t & 7) == 7) {
            int g = tid >> 8, rem = tid & 255, j = rem >> 1, half = rem & 1;
            float4 v = *(float4*)&s_out[(g * Vv + j) * 8 + half * 4];
            *(float4*)(outp + ((size_t)(b0 + g) * Vv + j) * Tt + (t - 7) + half * 4) = v;
            __syncthreads();
        }
    }
}

#define SMEM_BYTES (22656 * 4)

// ---------------- launch ----------------
extern "C" void kernel_launch(void* const* d_in, const int* in_sizes, int n_in,
                              void* d_out, int out_size)
{
    const float* x      = (const float*)d_in[0];
    const int*   y      = (const int*)  d_in[1];
    const float* emb    = (const float*)d_in[2];
    const float* attn_w = (const float*)d_in[3];
    const float* attn_b = (const float*)d_in[4];
    const float* comb_w = (const float*)d_in[5];
    const float* comb_b = (const float*)d_in[6];
    const float* gih    = (const float*)d_in[7];
    const float* ghh    = (const float*)d_in[8];
    const float* gbi    = (const float*)d_in[9];
    const float* gbh    = (const float*)d_in[10];
    const float* out_w  = (const float*)d_in[11];
    const float* out_b  = (const float*)d_in[12];

    float* outp  = (float*)d_out;                        // [B,V,T]
    float* attnp = (float*)d_out + (size_t)Bb * Vv * Tt; // [B,T,L]

    cudaFuncSetAttribute(decoder_kernel,
                         cudaFuncAttributeMaxDynamicSharedMemorySize, SMEM_BYTES);

    pack_kernel<<<(PACK_TOTAL + 255) / 256, 256>>>(attn_w, comb_w, gih, ghh, out_w);
    pack_enc_kernel<<<((size_t)Bb * Hh * Ld / 4 + 255) / 256, 256>>>(x);
    decoder_kernel<<<Bb / G, NTH, SMEM_BYTES>>>(y, emb, attn_b, comb_b, gbi, gbh,
                                                out_b, outp, attnp);
}

// round 6
// speedup vs baseline: 1.2018x; 1.2018x over previous
#include <cuda_runtime.h>
#include <cuda_fp16.h>
#include <math.h>

#define Bb   512
#define Hh   256
#define Ld   256
#define Tt   64
#define Vv   128
#define NL   2
#define G    4
#define NTH  512

// ---------------- packed fp16 weight scratch (transposed + k-interleaved) ------------
// P[(k4*N + j)*4 + c] = W[j*K + 4*k4 + c]; element type is __half (uint2 per 4 k).
#define OFF_ATTN 0          // 512x256  -> 131072
#define OFF_COMB 131072     // 512x256  -> 131072
#define OFF_GIH  262144     // 2 x 256x768 -> 393216
#define OFF_GHH  655360     // 2 x 256x768 -> 393216
#define OFF_OUT  1048576    // 256x128  -> 32768
#define PACK_TOTAL 1081344

__device__ __align__(16) __half g_pack[PACK_TOTAL];
__device__ __align__(16) __half g_enc[(size_t)Bb * Hh * Ld];   // fp16 encoder memory

__global__ void pack_kernel(const float* __restrict__ aw, const float* __restrict__ cw,
                            const float* __restrict__ gih, const float* __restrict__ ghh,
                            const float* __restrict__ ow)
{
    int i = blockIdx.x * blockDim.x + threadIdx.x;
    if (i >= PACK_TOTAL) return;
    float v;
    if (i < 131072) {                       // attn: K=512, N=256
        int c = i & 3, j = (i >> 2) & 255, k4 = i >> 10;
        v = aw[j * 512 + k4 * 4 + c];
    } else if (i < 262144) {                // comb: K=512, N=256
        int r = i - 131072;
        int c = r & 3, j = (r >> 2) & 255, k4 = r >> 10;
        v = cw[j * 512 + k4 * 4 + c];
    } else if (i < 655360) {                // gru ih: per layer K=256, N=768
        int r = i - 262144;
        int layer = r / 196608; int q = r % 196608;
        int c = q & 3; int t2 = q >> 2; int j = t2 % 768; int k4 = t2 / 768;
        v = gih[layer * 196608 + j * 256 + k4 * 4 + c];
    } else if (i < 1048576) {               // gru hh
        int r = i - 655360;
        int layer = r / 196608; int q = r % 196608;
        int c = q & 3; int t2 = q >> 2; int j = t2 % 768; int k4 = t2 / 768;
        v = ghh[layer * 196608 + j * 256 + k4 * 4 + c];
    } else {                                // out: K=256, N=128
        int r = i - 1048576;
        int c = r & 3, j = (r >> 2) & 127, k4 = r >> 9;
        v = ow[j * 256 + k4 * 4 + c];
    }
    g_pack[i] = __float2half(v);
}

// fp32 -> fp16 encoder pack
__global__ void pack_enc_kernel(const float* __restrict__ x)
{
    size_t i = (size_t)blockIdx.x * blockDim.x + threadIdx.x;   // i over float4s
    float4 v = ((const float4*)x)[i];
    __half2 h0 = __floats2half2_rn(v.x, v.y);
    __half2 h1 = __floats2half2_rn(v.z, v.w);
    uint2 o;
    o.x = *(unsigned*)&h0;
    o.y = *(unsigned*)&h1;
    ((uint2*)g_enc)[i] = o;
}

// ---------------- f32x2 packed math helpers (sm_10x FFMA2) ----------------
typedef unsigned long long u64;

__device__ __forceinline__ void fma2(u64& d, u64 a, u64 b) {
    asm("fma.rn.f32x2 %0, %1, %2, %0;" : "+l"(d) : "l"(a), "l"(b));
}
__device__ __forceinline__ float sum2(u64 v) {
    float lo = __uint_as_float((unsigned)v);
    float hi = __uint_as_float((unsigned)(v >> 32));
    return lo + hi;
}
// fp16x2 -> packed f32x2 (lo half -> low word)
__device__ __forceinline__ u64 cvt2(unsigned h) {
    __half2 hv = *(__half2*)&h;
    float2 f = __half22float2(hv);
    return ((u64)__float_as_uint(f.y) << 32) | (u64)__float_as_uint(f.x);
}

// ---------------- vectorized block reduction (4 values, 16 warps) ----------------
__device__ __forceinline__ void block_reduce4(float v[G], float* sm, int tid, bool is_max) {
    __syncthreads();
    #pragma unroll
    for (int g = 0; g < G; g++) {
        #pragma unroll
        for (int o = 16; o > 0; o >>= 1) {
            float oth = __shfl_xor_sync(0xffffffffu, v[g], o);
            v[g] = is_max ? fmaxf(v[g], oth) : (v[g] + oth);
        }
    }
    int wid = tid >> 5;
    if ((tid & 31) == 0) {
        #pragma unroll
        for (int g = 0; g < G; g++) sm[wid * G + g] = v[g];
    }
    __syncthreads();
    #pragma unroll
    for (int g = 0; g < G; g++) {
        float r = sm[g];
        #pragma unroll
        for (int w = 1; w < 16; w++)
            r = is_max ? fmaxf(r, sm[w * G + g]) : (r + sm[w * G + g]);
        v[g] = r;
    }
}

// ---------------- main persistent decoder kernel (R4 structure, fp16 weights) --------
__global__ __launch_bounds__(NTH)
void decoder_kernel(const int*   __restrict__ y,      // [B,T]
                    const float* __restrict__ emb,    // [V,H]
                    const float* __restrict__ attn_b, // [L]
                    const float* __restrict__ comb_b, // [H]
                    const float* __restrict__ gbi,    // [2,768]
                    const float* __restrict__ gbh,    // [2,768]
                    const float* __restrict__ out_b,  // [V]
                    float* __restrict__ outp,         // [B,V,T]
                    float* __restrict__ attnp)        // [B,T,L]
{
    __shared__ __align__(16) float s_e  [G][Hh];
    __shared__ __align__(16) float s_h  [NL][G][Hh];
    __shared__ __align__(16) float s_aw [G][Ld];
    __shared__ __align__(16) float s_app[G][Hh];
    __shared__ __align__(16) float s_x  [G][Hh];
    __shared__ __align__(16) float s_p2 [G][3][Hh];
    __shared__ __align__(16) float s_out[G][Vv][8];
    __shared__ float s_red[16 * G];

    const int tid  = threadIdx.x;
    const int wid  = tid >> 5;
    const int lane = tid & 31;
    const int jj   = tid & 255;
    const bool hi  = (tid >= 256);
    const int b0   = blockIdx.x * G;

    const __half* Pattn = g_pack + OFF_ATTN;
    const __half* Pcomb = g_pack + OFF_COMB;
    const __half* Pgih  = g_pack + OFF_GIH;
    const __half* Pghh  = g_pack + OFF_GHH;
    const __half* Pout  = g_pack + OFF_OUT;

    for (int i = tid; i < NL * G * Hh; i += NTH)
        (&s_h[0][0][0])[i] = 0.f;
    __syncthreads();

    for (int t = 0; t < Tt; t++) {
        // -------- embedding lookup (teacher forcing; SOS=0 at t=0) --------
        #pragma unroll
        for (int i = tid; i < G * Hh; i += NTH) {
            int g = i >> 8, h = i & 255;
            int tok = (t == 0) ? 0 : y[(b0 + g) * Tt + t - 1];
            s_e[g][h] = emb[tok * Hh + h];
        }
        __syncthreads();

        // -------- attention scores: lo half = e-part, hi half = h-part --------
        {
            u64 acc[G] = {0, 0, 0, 0};
            const uint2* W = (const uint2*)Pattn + (hi ? 64 * 256 : 0) + jj;
            const float* vb = hi ? &s_h[0][0][0] : &s_e[0][0];
            #pragma unroll 4
            for (int k4 = 0; k4 < 64; k4++) {
                uint2 wh = W[k4 * 256];
                u64 wx = cvt2(wh.x), wy = cvt2(wh.y);
                #pragma unroll
                for (int g = 0; g < G; g++) {
                    ulonglong2 xv = ((const ulonglong2*)(vb + g * Hh))[k4];
                    fma2(acc[g], wx, xv.x);
                    fma2(acc[g], wy, xv.y);
                }
            }
            if (hi) {
                #pragma unroll
                for (int g = 0; g < G; g++) s_p2[g][0][jj] = sum2(acc[g]);
            }
            __syncthreads();

            // softmax over L per row (true values live in lo half)
            float sc[G];
            #pragma unroll
            for (int g = 0; g < G; g++)
                sc[g] = hi ? -1e30f : (sum2(acc[g]) + s_p2[g][0][jj] + attn_b[jj]);
            float m[G];
            #pragma unroll
            for (int g = 0; g < G; g++) m[g] = sc[g];
            block_reduce4(m, s_red, tid, true);
            float p[G];
            #pragma unroll
            for (int g = 0; g < G; g++) p[g] = hi ? 0.f : __expf(sc[g] - m[g]);
            float s[G];
            #pragma unroll
            for (int g = 0; g < G; g++) s[g] = p[g];
            block_reduce4(s, s_red, tid, false);
            if (!hi) {
                #pragma unroll
                for (int g = 0; g < G; g++) {
                    float a = p[g] * (1.f / s[g]);
                    s_aw[g][jj] = a;
                    attnp[((size_t)(b0 + g) * Tt + t) * Ld + jj] = a;
                }
            }
            __syncthreads();
        }

        // -------- applied = aw @ enc (fp16 enc, warp owns fixed row g) --------
        {
            const int g = wid >> 2;                    // 4 warps per batch row
            const int hbase = (wid & 3) * 64;          // 64 h-values per warp
            const float4* awp = (const float4*)(s_aw[g]);
            const float4 A0 = awp[lane * 2];
            const float4 A1 = awp[lane * 2 + 1];
            const uint4* xrow =
                (const uint4*)(g_enc + ((size_t)(b0 + g) * Hh + hbase) * Ld) + lane;
            #pragma unroll
            for (int it = 0; it < 64; it += 8) {
                uint4 xv[8];
                #pragma unroll
                for (int u = 0; u < 8; u++) xv[u] = xrow[(it + u) * 32];
                float d[8];
                #pragma unroll
                for (int u = 0; u < 8; u++) {
                    float2 f0 = __half22float2(*(__half2*)&xv[u].x);
                    float2 f1 = __half22float2(*(__half2*)&xv[u].y);
                    float2 f2 = __half22float2(*(__half2*)&xv[u].z);
                    float2 f3 = __half22float2(*(__half2*)&xv[u].w);
                    d[u] = f0.x * A0.x + f0.y * A0.y + f1.x * A0.z + f1.y * A0.w
                         + f2.x * A1.x + f2.y * A1.y + f3.x * A1.z + f3.y * A1.w;
                }
                #pragma unroll
                for (int u = 0; u < 8; u++) {
                    #pragma unroll
                    for (int o = 16; o > 0; o >>= 1)
                        d[u] += __shfl_xor_sync(0xffffffffu, d[u], o);
                }
                if (lane == 0) {
                    #pragma unroll
                    for (int u = 0; u < 8; u++) s_app[g][hbase + it + u] = d[u];
                }
            }
        }
        __syncthreads();

        // -------- combine: lo half = applied-part, hi half = e-part --------
        {
            u64 acc[G] = {0, 0, 0, 0};
            const uint2* W = (const uint2*)Pcomb + (hi ? 64 * 256 : 0) + jj;
            const float* vb = hi ? &s_e[0][0] : &s_app[0][0];
            #pragma unroll 4
            for (int k4 = 0; k4 < 64; k4++) {
                uint2 wh = W[k4 * 256];
                u64 wx = cvt2(wh.x), wy = cvt2(wh.y);
                #pragma unroll
                for (int g = 0; g < G; g++) {
                    ulonglong2 xv = ((const ulonglong2*)(vb + g * Hh))[k4];
                    fma2(acc[g], wx, xv.x);
                    fma2(acc[g], wy, xv.y);
                }
            }
            if (hi) {
                #pragma unroll
                for (int g = 0; g < G; g++) s_p2[g][0][jj] = sum2(acc[g]);
            }
            __syncthreads();
            if (!hi) {
                const float bj = comb_b[jj];
                #pragma unroll
                for (int g = 0; g < G; g++)
                    s_x[g][jj] = fmaxf(sum2(acc[g]) + s_p2[g][0][jj] + bj, 0.f);
            }
            __syncthreads();
        }

        // -------- GRU layers: lo half = ih matvec, hi half = hh matvec --------
        #pragma unroll
        for (int l = 0; l < NL; l++) {
            u64 a0[G] = {0,0,0,0}, a1[G] = {0,0,0,0}, a2[G] = {0,0,0,0};
            const uint2* W =
                (const uint2*)((hi ? Pghh : Pgih) + l * 196608) + jj;
            const float* vb = hi ? &s_h[l][0][0] : &s_x[0][0];
            #pragma unroll 2
            for (int k4 = 0; k4 < 64; k4++) {
                uint2 wh0 = W[k4 * 768];
                uint2 wh1 = W[k4 * 768 + 256];
                uint2 wh2 = W[k4 * 768 + 512];
                u64 w0x = cvt2(wh0.x), w0y = cvt2(wh0.y);
                u64 w1x = cvt2(wh1.x), w1y = cvt2(wh1.y);
                u64 w2x = cvt2(wh2.x), w2y = cvt2(wh2.y);
                #pragma unroll
                for (int g = 0; g < G; g++) {
                    ulonglong2 xv = ((const ulonglong2*)(vb + g * Hh))[k4];
                    fma2(a0[g], w0x, xv.x); fma2(a0[g], w0y, xv.y);
                    fma2(a1[g], w1x, xv.x); fma2(a1[g], w1y, xv.y);
                    fma2(a2[g], w2x, xv.x); fma2(a2[g], w2y, xv.y);
                }
            }
            if (hi) {
                #pragma unroll
                for (int g = 0; g < G; g++) {
                    s_p2[g][0][jj] = sum2(a0[g]);
                    s_p2[g][1][jj] = sum2(a1[g]);
                    s_p2[g][2][jj] = sum2(a2[g]);
                }
            }
            __syncthreads();
            if (!hi) {
                const float bi0 = gbi[l * 768 + jj];
                const float bi1 = gbi[l * 768 + 256 + jj];
                const float bi2 = gbi[l * 768 + 512 + jj];
                const float bh0 = gbh[l * 768 + jj];
                const float bh1 = gbh[l * 768 + 256 + jj];
                const float bh2 = gbh[l * 768 + 512 + jj];
                #pragma unroll
                for (int g = 0; g < G; g++) {
                    float hprev = s_h[l][g][jj];
                    float i0 = sum2(a0[g]) + bi0, h0 = s_p2[g][0][jj] + bh0;
                    float i1 = sum2(a1[g]) + bi1, h1 = s_p2[g][1][jj] + bh1;
                    float i2 = sum2(a2[g]) + bi2, h2 = s_p2[g][2][jj] + bh2;
                    float r = 1.f / (1.f + __expf(-(i0 + h0)));
                    float z = 1.f / (1.f + __expf(-(i1 + h1)));
                    float n = tanhf(i2 + r * h2);
                    float hn = (1.f - z) * n + z * hprev;
                    s_h[l][g][jj] = hn;
                    s_x[g][jj]    = hn;
                }
            }
            __syncthreads();
        }

        // -------- output projection (K split 4 ways) + log_softmax --------
        {
            int j  = tid & 127;
            int sl = tid >> 7;
            u64 acc[G] = {0, 0, 0, 0};
            const uint2* W = (const uint2*)Pout + j;
            #pragma unroll 4
            for (int k4 = sl * 16; k4 < sl * 16 + 16; k4++) {
                uint2 wh = W[k4 * 128];
                u64 wx = cvt2(wh.x), wy = cvt2(wh.y);
                #pragma unroll
                for (int g = 0; g < G; g++) {
                    ulonglong2 hv = ((const ulonglong2*)s_x[g])[k4];
                    fma2(acc[g], wx, hv.x);
                    fma2(acc[g], wy, hv.y);
                }
            }
            float* s_op = &s_p2[0][0][0];
            #pragma unroll
            for (int g = 0; g < G; g++) s_op[(g * 4 + sl) * 128 + j] = sum2(acc[g]);
            __syncthreads();

            float oacc[G];
            #pragma unroll
            for (int g = 0; g < G; g++) {
                oacc[g] = (tid < 128)
                    ? (out_b[j] + s_op[(g * 4 + 0) * 128 + j] + s_op[(g * 4 + 1) * 128 + j]
                               + s_op[(g * 4 + 2) * 128 + j] + s_op[(g * 4 + 3) * 128 + j])
                    : -1e30f;
            }
            float m[G];
            #pragma unroll
            for (int g = 0; g < G; g++) m[g] = oacc[g];
            block_reduce4(m, s_red, tid, true);
            float p[G];
            #pragma unroll
            for (int g = 0; g < G; g++) p[g] = (tid < 128) ? __expf(oacc[g] - m[g]) : 0.f;
            float s[G];
            #pragma unroll
            for (int g = 0; g < G; g++) s[g] = p[g];
            block_reduce4(s, s_red, tid, false);
            if (tid < 128) {
                #pragma unroll
                for (int g = 0; g < G; g++)
                    s_out[g][j][t & 7] = oacc[g] - m[g] - logf(s[g]);
            }
        }

        // -------- flush staged outputs every 8 steps (coalesced float4 x2) --------
        __syncthreads();
        if ((t & 7) == 7) {
            int g = tid >> 7, j = tid & 127;
            float4 v0 = *(float4*)&s_out[g][j][0];
            float4 v1 = *(float4*)&s_out[g][j][4];
            float4* dst = (float4*)(outp + ((size_t)(b0 + g) * Vv + j) * Tt + (t - 7));
            dst[0] = v0;
            dst[1] = v1;
            __syncthreads();
        }
    }
}

// ---------------- launch ----------------
extern "C" void kernel_launch(void* const* d_in, const int* in_sizes, int n_in,
                              void* d_out, int out_size)
{
    const float* x      = (const float*)d_in[0];
    const int*   y      = (const int*)  d_in[1];
    const float* emb    = (const float*)d_in[2];
    const float* attn_w = (const float*)d_in[3];
    const float* attn_b = (const float*)d_in[4];
    const float* comb_w = (const float*)d_in[5];
    const float* comb_b = (const float*)d_in[6];
    const float* gih    = (const float*)d_in[7];
    const float* ghh    = (const float*)d_in[8];
    const float* gbi    = (const float*)d_in[9];
    const float* gbh    = (const float*)d_in[10];
    const float* out_w  = (const float*)d_in[11];
    const float* out_b  = (const float*)d_in[12];

    float* outp  = (float*)d_out;                        // [B,V,T]
    float* attnp = (float*)d_out + (size_t)Bb * Vv * Tt; // [B,T,L]

    pack_kernel<<<(PACK_TOTAL + 255) / 256, 256>>>(attn_w, comb_w, gih, ghh, out_w);
    pack_enc_kernel<<<((size_t)Bb * Hh * Ld / 4 + 255) / 256, 256>>>(x);
    decoder_kernel<<<Bb / G, NTH>>>(y, emb, attn_b, comb_b, gbi, gbh, out_b, outp, attnp);
}

// round 7
// speedup vs baseline: 1.2250x; 1.0193x over previous
#include <cuda_runtime.h>
#include <cuda_fp16.h>
#include <math.h>

#define Bb   512
#define Hh   256
#define Ld   256
#define Tt   64
#define Vv   128
#define NL   2
#define G    4
#define NTH  512

// ---------------- packed fp16 weight scratch (transposed + k-interleaved) ------------
// P[(k4*N + j)*4 + c] = W[j*K + 4*k4 + c]; element type is __half (uint2 per 4 k).
#define OFF_ATTN 0          // 512x256  -> 131072
#define OFF_COMB 131072     // 512x256  -> 131072
#define OFF_GIH  262144     // 2 x 256x768 -> 393216
#define OFF_GHH  655360     // 2 x 256x768 -> 393216
#define OFF_OUT  1048576    // 256x128  -> 32768
#define PACK_TOTAL 1081344

__device__ __align__(16) __half g_pack[PACK_TOTAL];
__device__ __align__(16) __half g_enc[(size_t)Bb * Hh * Ld];   // fp16 encoder memory

__global__ void pack_kernel(const float* __restrict__ aw, const float* __restrict__ cw,
                            const float* __restrict__ gih, const float* __restrict__ ghh,
                            const float* __restrict__ ow)
{
    int i = blockIdx.x * blockDim.x + threadIdx.x;
    if (i >= PACK_TOTAL) return;
    float v;
    if (i < 131072) {                       // attn: K=512, N=256
        int c = i & 3, j = (i >> 2) & 255, k4 = i >> 10;
        v = aw[j * 512 + k4 * 4 + c];
    } else if (i < 262144) {                // comb: K=512, N=256
        int r = i - 131072;
        int c = r & 3, j = (r >> 2) & 255, k4 = r >> 10;
        v = cw[j * 512 + k4 * 4 + c];
    } else if (i < 655360) {                // gru ih: per layer K=256, N=768
        int r = i - 262144;
        int layer = r / 196608; int q = r % 196608;
        int c = q & 3; int t2 = q >> 2; int j = t2 % 768; int k4 = t2 / 768;
        v = gih[layer * 196608 + j * 256 + k4 * 4 + c];
    } else if (i < 1048576) {               // gru hh
        int r = i - 655360;
        int layer = r / 196608; int q = r % 196608;
        int c = q & 3; int t2 = q >> 2; int j = t2 % 768; int k4 = t2 / 768;
        v = ghh[layer * 196608 + j * 256 + k4 * 4 + c];
    } else {                                // out: K=256, N=128
        int r = i - 1048576;
        int c = r & 3, j = (r >> 2) & 127, k4 = r >> 9;
        v = ow[j * 256 + k4 * 4 + c];
    }
    g_pack[i] = __float2half(v);
}

// fp32 -> fp16 encoder pack
__global__ void pack_enc_kernel(const float* __restrict__ x)
{
    size_t i = (size_t)blockIdx.x * blockDim.x + threadIdx.x;   // i over float4s
    float4 v = ((const float4*)x)[i];
    __half2 h0 = __floats2half2_rn(v.x, v.y);
    __half2 h1 = __floats2half2_rn(v.z, v.w);
    uint2 o;
    o.x = *(unsigned*)&h0;
    o.y = *(unsigned*)&h1;
    ((uint2*)g_enc)[i] = o;
}

// ---------------- f32x2 packed math helpers (sm_10x FFMA2) ----------------
typedef unsigned long long u64;

__device__ __forceinline__ void fma2(u64& d, u64 a, u64 b) {
    asm("fma.rn.f32x2 %0, %1, %2, %0;" : "+l"(d) : "l"(a), "l"(b));
}
__device__ __forceinline__ float sum2(u64 v) {
    float lo = __uint_as_float((unsigned)v);
    float hi = __uint_as_float((unsigned)(v >> 32));
    return lo + hi;
}
// fp16x2 -> packed f32x2 (lo half -> low word)
__device__ __forceinline__ u64 cvt2(unsigned h) {
    __half2 hv = *(__half2*)&h;
    float2 f = __half22float2(hv);
    return ((u64)__float_as_uint(f.y) << 32) | (u64)__float_as_uint(f.x);
}

// ---------------- vectorized block reduction (4 values, 16 warps) ----------------
__device__ __forceinline__ void block_reduce4(float v[G], float* sm, int tid, bool is_max) {
    __syncthreads();
    #pragma unroll
    for (int g = 0; g < G; g++) {
        #pragma unroll
        for (int o = 16; o > 0; o >>= 1) {
            float oth = __shfl_xor_sync(0xffffffffu, v[g], o);
            v[g] = is_max ? fmaxf(v[g], oth) : (v[g] + oth);
        }
    }
    int wid = tid >> 5;
    if ((tid & 31) == 0) {
        #pragma unroll
        for (int g = 0; g < G; g++) sm[wid * G + g] = v[g];
    }
    __syncthreads();
    #pragma unroll
    for (int g = 0; g < G; g++) {
        float r = sm[g];
        #pragma unroll
        for (int w = 1; w < 16; w++)
            r = is_max ? fmaxf(r, sm[w * G + g]) : (r + sm[w * G + g]);
        v[g] = r;
    }
}

// ---------------- main persistent decoder kernel ----------------
__global__ __launch_bounds__(NTH)
void decoder_kernel(const int*   __restrict__ y,      // [B,T]
                    const float* __restrict__ emb,    // [V,H]
                    const float* __restrict__ attn_b, // [L]
                    const float* __restrict__ comb_b, // [H]
                    const float* __restrict__ gbi,    // [2,768]
                    const float* __restrict__ gbh,    // [2,768]
                    const float* __restrict__ out_b,  // [V]
                    float* __restrict__ outp,         // [B,V,T]
                    float* __restrict__ attnp)        // [B,T,L]
{
    __shared__ __align__(16) float s_e  [G][Hh];
    __shared__ __align__(16) float s_h  [NL][G][Hh];
    __shared__ __align__(16) float s_aw [G][Ld];
    __shared__ __align__(16) float s_app[G][Hh];
    __shared__ __align__(16) float s_x  [G][Hh];
    __shared__ __align__(16) float s_p2 [G][3][Hh];
    __shared__ __align__(16) float s_out[G][Vv][8];
    __shared__ float s_red[16 * G];

    const int tid  = threadIdx.x;
    const int wid  = tid >> 5;
    const int lane = tid & 31;
    const int jj   = tid & 255;
    const bool hi  = (tid >= 256);
    const int b0   = blockIdx.x * G;

    const __half* Pattn = g_pack + OFF_ATTN;
    const __half* Pcomb = g_pack + OFF_COMB;
    const __half* Pgih  = g_pack + OFF_GIH;
    const __half* Pghh  = g_pack + OFF_GHH;
    const __half* Pout  = g_pack + OFF_OUT;

    for (int i = tid; i < NL * G * Hh; i += NTH)
        (&s_h[0][0][0])[i] = 0.f;
    __syncthreads();

    for (int t = 0; t < Tt; t++) {
        // -------- embedding lookup (teacher forcing; SOS=0 at t=0) --------
        #pragma unroll
        for (int i = tid; i < G * Hh; i += NTH) {
            int g = i >> 8, h = i & 255;
            int tok = (t == 0) ? 0 : y[(b0 + g) * Tt + t - 1];
            s_e[g][h] = emb[tok * Hh + h];
        }
        __syncthreads();

        // -------- attention scores: lo half = e-part, hi half = h-part --------
        {
            u64 acc[G] = {0, 0, 0, 0};
            const uint2* W = (const uint2*)Pattn + (hi ? 64 * 256 : 0) + jj;
            const float* vb = hi ? &s_h[0][0][0] : &s_e[0][0];
            #pragma unroll 8
            for (int k4 = 0; k4 < 64; k4++) {
                uint2 wh = W[k4 * 256];
                u64 wx = cvt2(wh.x), wy = cvt2(wh.y);
                #pragma unroll
                for (int g = 0; g < G; g++) {
                    ulonglong2 xv = ((const ulonglong2*)(vb + g * Hh))[k4];
                    fma2(acc[g], wx, xv.x);
                    fma2(acc[g], wy, xv.y);
                }
            }
            if (hi) {
                #pragma unroll
                for (int g = 0; g < G; g++) s_p2[g][0][jj] = sum2(acc[g]);
            }
            __syncthreads();

            // softmax over L per row (true values live in lo half)
            float sc[G];
            #pragma unroll
            for (int g = 0; g < G; g++)
                sc[g] = hi ? -1e30f : (sum2(acc[g]) + s_p2[g][0][jj] + attn_b[jj]);
            float m[G];
            #pragma unroll
            for (int g = 0; g < G; g++) m[g] = sc[g];
            block_reduce4(m, s_red, tid, true);
            float p[G];
            #pragma unroll
            for (int g = 0; g < G; g++) p[g] = hi ? 0.f : __expf(sc[g] - m[g]);
            float s[G];
            #pragma unroll
            for (int g = 0; g < G; g++) s[g] = p[g];
            block_reduce4(s, s_red, tid, false);
            if (!hi) {
                #pragma unroll
                for (int g = 0; g < G; g++) {
                    float a = p[g] * (1.f / s[g]);
                    s_aw[g][jj] = a;
                    attnp[((size_t)(b0 + g) * Tt + t) * Ld + jj] = a;
                }
            }
            __syncthreads();
        }

        // -------- applied = aw @ enc (fp16 enc, warp owns fixed row g) --------
        {
            const int g = wid >> 2;                    // 4 warps per batch row
            const int hbase = (wid & 3) * 64;          // 64 h-values per warp
            const float4* awp = (const float4*)(s_aw[g]);
            const float4 A0 = awp[lane * 2];
            const float4 A1 = awp[lane * 2 + 1];
            const uint4* xrow =
                (const uint4*)(g_enc + ((size_t)(b0 + g) * Hh + hbase) * Ld) + lane;
            #pragma unroll
            for (int it = 0; it < 64; it += 8) {
                uint4 xv[8];
                #pragma unroll
                for (int u = 0; u < 8; u++) xv[u] = xrow[(it + u) * 32];
                float d[8];
                #pragma unroll
                for (int u = 0; u < 8; u++) {
                    float2 f0 = __half22float2(*(__half2*)&xv[u].x);
                    float2 f1 = __half22float2(*(__half2*)&xv[u].y);
                    float2 f2 = __half22float2(*(__half2*)&xv[u].z);
                    float2 f3 = __half22float2(*(__half2*)&xv[u].w);
                    d[u] = f0.x * A0.x + f0.y * A0.y + f1.x * A0.z + f1.y * A0.w
                         + f2.x * A1.x + f2.y * A1.y + f3.x * A1.z + f3.y * A1.w;
                }
                #pragma unroll
                for (int u = 0; u < 8; u++) {
                    #pragma unroll
                    for (int o = 16; o > 0; o >>= 1)
                        d[u] += __shfl_xor_sync(0xffffffffu, d[u], o);
                }
                if (lane == 0) {
                    #pragma unroll
                    for (int u = 0; u < 8; u++) s_app[g][hbase + it + u] = d[u];
                }
            }
        }
        __syncthreads();

        // -------- combine: lo half = applied-part, hi half = e-part --------
        {
            u64 acc[G] = {0, 0, 0, 0};
            const uint2* W = (const uint2*)Pcomb + (hi ? 64 * 256 : 0) + jj;
            const float* vb = hi ? &s_e[0][0] : &s_app[0][0];
            #pragma unroll 8
            for (int k4 = 0; k4 < 64; k4++) {
                uint2 wh = W[k4 * 256];
                u64 wx = cvt2(wh.x), wy = cvt2(wh.y);
                #pragma unroll
                for (int g = 0; g < G; g++) {
                    ulonglong2 xv = ((const ulonglong2*)(vb + g * Hh))[k4];
                    fma2(acc[g], wx, xv.x);
                    fma2(acc[g], wy, xv.y);
                }
            }
            if (hi) {
                #pragma unroll
                for (int g = 0; g < G; g++) s_p2[g][0][jj] = sum2(acc[g]);
            }
            __syncthreads();
            if (!hi) {
                const float bj = comb_b[jj];
                #pragma unroll
                for (int g = 0; g < G; g++)
                    s_x[g][jj] = fmaxf(sum2(acc[g]) + s_p2[g][0][jj] + bj, 0.f);
            }
            __syncthreads();
        }

        // -------- GRU layers: lo half = ih matvec, hi half = hh matvec --------
        #pragma unroll
        for (int l = 0; l < NL; l++) {
            u64 a0[G] = {0,0,0,0}, a1[G] = {0,0,0,0}, a2[G] = {0,0,0,0};
            const uint2* W =
                (const uint2*)((hi ? Pghh : Pgih) + l * 196608) + jj;
            const float* vb = hi ? &s_h[l][0][0] : &s_x[0][0];
            #pragma unroll 4
            for (int k4 = 0; k4 < 64; k4++) {
                uint2 wh0 = W[k4 * 768];
                uint2 wh1 = W[k4 * 768 + 256];
                uint2 wh2 = W[k4 * 768 + 512];
                u64 w0x = cvt2(wh0.x), w0y = cvt2(wh0.y);
                u64 w1x = cvt2(wh1.x), w1y = cvt2(wh1.y);
                u64 w2x = cvt2(wh2.x), w2y = cvt2(wh2.y);
                #pragma unroll
                for (int g = 0; g < G; g++) {
                    ulonglong2 xv = ((const ulonglong2*)(vb + g * Hh))[k4];
                    fma2(a0[g], w0x, xv.x); fma2(a0[g], w0y, xv.y);
                    fma2(a1[g], w1x, xv.x); fma2(a1[g], w1y, xv.y);
                    fma2(a2[g], w2x, xv.x); fma2(a2[g], w2y, xv.y);
                }
            }
            if (hi) {
                #pragma unroll
                for (int g = 0; g < G; g++) {
                    s_p2[g][0][jj] = sum2(a0[g]);
                    s_p2[g][1][jj] = sum2(a1[g]);
                    s_p2[g][2][jj] = sum2(a2[g]);
                }
            }
            __syncthreads();
            if (!hi) {
                const float bi0 = gbi[l * 768 + jj];
                const float bi1 = gbi[l * 768 + 256 + jj];
                const float bi2 = gbi[l * 768 + 512 + jj];
                const float bh0 = gbh[l * 768 + jj];
                const float bh1 = gbh[l * 768 + 256 + jj];
                const float bh2 = gbh[l * 768 + 512 + jj];
                #pragma unroll
                for (int g = 0; g < G; g++) {
                    float hprev = s_h[l][g][jj];
                    float i0 = sum2(a0[g]) + bi0, h0 = s_p2[g][0][jj] + bh0;
                    float i1 = sum2(a1[g]) + bi1, h1 = s_p2[g][1][jj] + bh1;
                    float i2 = sum2(a2[g]) + bi2, h2 = s_p2[g][2][jj] + bh2;
                    float r = 1.f / (1.f + __expf(-(i0 + h0)));
                    float z = 1.f / (1.f + __expf(-(i1 + h1)));
                    float n = tanhf(i2 + r * h2);
                    float hn = (1.f - z) * n + z * hprev;
                    s_h[l][g][jj] = hn;
                    s_x[g][jj]    = hn;
                }
            }
            __syncthreads();
        }

        // -------- output projection (K split 4 ways) + log_softmax --------
        {
            int j  = tid & 127;
            int sl = tid >> 7;
            u64 acc[G] = {0, 0, 0, 0};
            const uint2* W = (const uint2*)Pout + j;
            #pragma unroll 8
            for (int k4 = sl * 16; k4 < sl * 16 + 16; k4++) {
                uint2 wh = W[k4 * 128];
                u64 wx = cvt2(wh.x), wy = cvt2(wh.y);
                #pragma unroll
                for (int g = 0; g < G; g++) {
                    ulonglong2 hv = ((const ulonglong2*)s_x[g])[k4];
                    fma2(acc[g], wx, hv.x);
                    fma2(acc[g], wy, hv.y);
                }
            }
            float* s_op = &s_p2[0][0][0];
            #pragma unroll
            for (int g = 0; g < G; g++) s_op[(g * 4 + sl) * 128 + j] = sum2(acc[g]);
            __syncthreads();

            float oacc[G];
            #pragma unroll
            for (int g = 0; g < G; g++) {
                oacc[g] = (tid < 128)
                    ? (out_b[j] + s_op[(g * 4 + 0) * 128 + j] + s_op[(g * 4 + 1) * 128 + j]
                               + s_op[(g * 4 + 2) * 128 + j] + s_op[(g * 4 + 3) * 128 + j])
                    : -1e30f;
            }
            float m[G];
            #pragma unroll
            for (int g = 0; g < G; g++) m[g] = oacc[g];
            block_reduce4(m, s_red, tid, true);
            float p[G];
            #pragma unroll
            for (int g = 0; g < G; g++) p[g] = (tid < 128) ? __expf(oacc[g] - m[g]) : 0.f;
            float s[G];
            #pragma unroll
            for (int g = 0; g < G; g++) s[g] = p[g];
            block_reduce4(s, s_red, tid, false);
            if (tid < 128) {
                #pragma unroll
                for (int g = 0; g < G; g++)
                    s_out[g][j][t & 7] = oacc[g] - m[g] - logf(s[g]);
            }
        }

        // -------- flush staged outputs every 8 steps (coalesced float4 x2) --------
        __syncthreads();
        if ((t & 7) == 7) {
            int g = tid >> 7, j = tid & 127;
            float4 v0 = *(float4*)&s_out[g][j][0];
            float4 v1 = *(float4*)&s_out[g][j][4];
            float4* dst = (float4*)(outp + ((size_t)(b0 + g) * Vv + j) * Tt + (t - 7));
            dst[0] = v0;
            dst[1] = v1;
            __syncthreads();
        }
    }
}

// ---------------- launch ----------------
extern "C" void kernel_launch(void* const* d_in, const int* in_sizes, int n_in,
                              void* d_out, int out_size)
{
    const float* x      = (const float*)d_in[0];
    const int*   y      = (const int*)  d_in[1];
    const float* emb    = (const float*)d_in[2];
    const float* attn_w = (const float*)d_in[3];
    const float* attn_b = (const float*)d_in[4];
    const float* comb_w = (const float*)d_in[5];
    const float* comb_b = (const float*)d_in[6];
    const float* gih    = (const float*)d_in[7];
    const float* ghh    = (const float*)d_in[8];
    const float* gbi    = (const float*)d_in[9];
    const float* gbh    = (const float*)d_in[10];
    const float* out_w  = (const float*)d_in[11];
    const float* out_b  = (const float*)d_in[12];

    float* outp  = (float*)d_out;                        // [B,V,T]
    float* attnp = (float*)d_out + (size_t)Bb * Vv * Tt; // [B,T,L]

    pack_kernel<<<(PACK_TOTAL + 255) / 256, 256>>>(attn_w, comb_w, gih, ghh, out_w);
    pack_enc_kernel<<<((size_t)Bb * Hh * Ld / 4 + 255) / 256, 256>>>(x);
    decoder_kernel<<<Bb / G, NTH>>>(y, emb, attn_b, comb_b, gbi, gbh, out_b, outp, attnp);
}